// round 2
// baseline (speedup 1.0000x reference)
#include <cuda_runtime.h>

// Problem constants (fixed shapes from reference)
#define Bn 16
#define In 32
#define Cn 8
#define Jn 10
#define Dn 16
#define Hn 6
#define Wn 6
#define Xn 576   // D*H*W
#define XH 288   // half of X (one CTA handles one half)
#define HWn 36   // H*W
#define EPSf 1e-7f

// Scratch (device globals; no allocation inside kernel_launch)
__device__ float g_U[(size_t)Bn*Jn*In*Xn];   // [b][j][i][x], 11.8 MB
__device__ float g_cT[Jn*In];                // coupling coeffs, transposed [j][i]
__device__ float g_nPart[Bn*Jn*2];           // per-(b,j,half) partial L1 norms of s
__device__ float g_aPart[(size_t)Bn*Jn*2*In];// per-(b,j,half) partial agreement[i]
__device__ float g_bij[In*Jn];               // routing logits [i][j]
__device__ float g_s3[(size_t)Bn*Jn*Xn];     // final-iteration s

// Block-wide sum for 288 threads (9 warps). Result valid on thread 0 only.
__device__ __forceinline__ float blockReduceSum288(float v) {
    __shared__ float red[9];
    int lane = threadIdx.x & 31, w = threadIdx.x >> 5;
    #pragma unroll
    for (int o = 16; o > 0; o >>= 1) v += __shfl_down_sync(0xffffffffu, v, o);
    if (lane == 0) red[w] = v;
    __syncthreads();
    float s = 0.f;
    if (threadIdx.x == 0) {
        #pragma unroll
        for (int i = 0; i < 9; i++) s += red[i];
    }
    return s;
}

__device__ __forceinline__ float squash_k(float n) {
    float n2 = n * n;
    return (n2 / (1.f + n2)) / (n + EPSf);
}

// K1: stream u_hat (94 MB), build U = sum_c u_hat, write U, fuse iter-1 s
// (c1 == 1/J exactly since b_ij starts at 0), emit L1-norm partials.
// grid = 320 (= (b*Jn + j)*2 + half), block = 288 (1 thread per x)
__global__ void __launch_bounds__(XH) k1(const float* __restrict__ u,
                                         const float* __restrict__ bias) {
    __shared__ float Us[In][XH + 1];
    int bj = blockIdx.x >> 1;
    int half = blockIdx.x & 1;
    int b = bj / Jn, j = bj % Jn;
    int x = threadIdx.x;
    int xg = half * XH + x;

    // u_hat index: ((b*In + i)*Cn + c)*Jn*Xn + j*Xn + xg
    const float* base = u + ((size_t)b * In) * Cn * Jn * Xn + (size_t)j * Xn + xg;
    for (int i = 0; i < In; i++) {
        const float* p = base + (size_t)i * Cn * Jn * Xn;
        float acc = 0.f;
        #pragma unroll
        for (int c = 0; c < Cn; c++) acc += p[(size_t)c * Jn * Xn];
        Us[i][x] = acc;
        g_U[((size_t)bj * In + i) * Xn + xg] = acc;
    }
    __syncthreads();

    // s1 = (1/J) * sum_i U[i][x] + bias[j][d]
    float s = 0.f;
    #pragma unroll
    for (int i = 0; i < In; i++) s += Us[i][x];
    s = s * (1.0f / Jn) + bias[j * Dn + xg / HWn];

    float n = blockReduceSum288(fabsf(s));
    if (threadIdx.x == 0) g_nPart[bj * 2 + half] = n;

    // initialize coupling coefficients for iteration 1 (softmax of zeros).
    // NOTE: Jn*In = 320 > blockDim (288), so stride the init.
    if (blockIdx.x == 0)
        for (int t = threadIdx.x; t < Jn * In; t += XH) g_cT[t] = 1.0f / Jn;
}

// KA: agreement pass. Recompute s from smem-cached U, scale by k_b, emit
// per-(b,j,half) agreement partials (deterministic, no atomics).
// grid = 320, block = 288
__global__ void __launch_bounds__(XH) ka(const float* __restrict__ bias) {
    __shared__ float Us[In][XH + 1];
    __shared__ float ss[XH];
    __shared__ float cs[In];
    __shared__ float kb;
    int bj = blockIdx.x >> 1;
    int half = blockIdx.x & 1;
    int b = bj / Jn, j = bj % Jn;
    int x = threadIdx.x;

    for (int i = 0; i < In; i++)
        Us[i][x] = g_U[((size_t)bj * In + i) * Xn + half * XH + x];
    if (x < In) cs[x] = g_cT[j * In + x];
    if (x == 0) {
        float n = 0.f;
        #pragma unroll
        for (int t = 0; t < Jn * 2; t++) n += g_nPart[b * Jn * 2 + t];
        kb = squash_k(n);
    }
    __syncthreads();

    float s = 0.f;
    #pragma unroll
    for (int i = 0; i < In; i++) s += cs[i] * Us[i][x];
    ss[x] = s + bias[j * Dn + (half * XH + x) / HWn];
    __syncthreads();

    // a[i] = k_b * sum_x U[i][x] * s[x] ; warps 0..7 each own 4 rows of i
    int w = threadIdx.x >> 5, lane = threadIdx.x & 31;
    if (w < 8) {
        #pragma unroll
        for (int ii = 0; ii < 4; ii++) {
            int i = w * 4 + ii;
            float a = 0.f;
            #pragma unroll
            for (int xx = lane; xx < XH; xx += 32) a += Us[i][xx] * ss[xx];
            #pragma unroll
            for (int o = 16; o > 0; o >>= 1) a += __shfl_down_sync(0xffffffffu, a, o);
            if (lane == 0) g_aPart[(size_t)blockIdx.x * In + i] = kb * a;
        }
    }
}

// Tc: tiny routing update. agreement reduce (fixed order) -> b_ij update ->
// softmax over j -> new coupling coeffs. 1 block, 320 threads.
__global__ void tc(int first) {
    __shared__ float sb[In * Jn];
    int t = threadIdx.x;
    int i = t / Jn, j = t % Jn;
    float a = 0.f;
    #pragma unroll
    for (int b = 0; b < Bn; b++)
        #pragma unroll
        for (int hf = 0; hf < 2; hf++)
            a += g_aPart[(size_t)((b * Jn + j) * 2 + hf) * In + i];
    float bij = first ? a : (g_bij[t] + a);
    g_bij[t] = bij;
    sb[t] = bij;
    __syncthreads();
    float mx = -1e30f;
    #pragma unroll
    for (int jj = 0; jj < Jn; jj++) mx = fmaxf(mx, sb[i * Jn + jj]);
    float den = 0.f;
    #pragma unroll
    for (int jj = 0; jj < Jn; jj++) den += expf(sb[i * Jn + jj] - mx);
    g_cT[j * In + i] = expf(sb[t] - mx) / den;
}

// KS: s pass over U only (streamed from global, no smem tile needed).
// Emits L1-norm partials; on the final iteration also stores s.
// grid = 320, block = 288
__global__ void __launch_bounds__(XH) ks(const float* __restrict__ bias, int write_s) {
    __shared__ float cs[In];
    int bj = blockIdx.x >> 1;
    int half = blockIdx.x & 1;
    int j = bj % Jn;
    int x = threadIdx.x;
    if (x < In) cs[x] = g_cT[j * In + x];
    __syncthreads();

    const float* Up = &g_U[((size_t)bj * In) * Xn + half * XH + x];
    float s = 0.f;
    #pragma unroll
    for (int i = 0; i < In; i++) s += cs[i] * Up[(size_t)i * Xn];
    s += bias[j * Dn + (half * XH + x) / HWn];
    if (write_s) g_s3[(size_t)bj * Xn + half * XH + x] = s;

    float n = blockReduceSum288(fabsf(s));
    if (threadIdx.x == 0) g_nPart[bj * 2 + half] = n;
}

// Kv: final squash: v = k_b * s3. k_b recomputed per thread from the 20 hot
// nPart entries (L1-resident).
__global__ void kv(float* __restrict__ out) {
    int idx = blockIdx.x * blockDim.x + threadIdx.x;
    if (idx >= Bn * Jn * Xn) return;
    int b = idx / (Jn * Xn);
    float n = 0.f;
    #pragma unroll
    for (int t = 0; t < Jn * 2; t++) n += g_nPart[b * Jn * 2 + t];
    out[idx] = squash_k(n) * g_s3[idx];
}

extern "C" void kernel_launch(void* const* d_in, const int* in_sizes, int n_in,
                              void* d_out, int out_size) {
    const float* u    = (const float*)d_in[0];
    const float* bias = (const float*)d_in[1];
    float* out = (float*)d_out;
    // num_routing is a baked constant (3); d_in[2] (if present) is ignored.

    // iter 1: s fused into K1 (c1 uniform), then agreement + routing update
    k1<<<320, 288>>>(u, bias);
    ka<<<320, 288>>>(bias);
    tc<<<1, 320>>>(1);
    // iter 2
    ks<<<320, 288>>>(bias, 0);
    ka<<<320, 288>>>(bias);
    tc<<<1, 320>>>(0);
    // iter 3: only s + squash needed (final agreement is dead in reference)
    ks<<<320, 288>>>(bias, 1);
    kv<<<360, 256>>>(out);
}

// round 4
// speedup vs baseline: 1.0361x; 1.0361x over previous
#include <cuda_runtime.h>

// Shapes (fixed)
#define Bn 16
#define In 32
#define Cn 8
#define Jn 10
#define Dn 16
#define Xn 576   // D*H*W
#define XH 288   // half handled per CTA
#define HWn 36
#define EPSf 1e-7f
#define GRID (Bn*Jn*2)   // 320 CTAs

// Cross-CTA communication scratch, DOUBLE-BUFFERED by iteration parity to kill
// the WAR race across the single per-iteration grid barrier.
__device__ float    g_nPart[2][GRID];        // per-(b,j,half) L1-norm partial of s
__device__ float    g_aPart[2][GRID * In];   // per-(b,j,half) unscaled agreement[i]
__device__ unsigned g_cnt;                   // barrier arrival counter (self-resetting)
__device__ unsigned g_gen;                   // barrier generation (monotonic)

__device__ __forceinline__ float squash_k(float n) {
    float n2 = n * n;
    return (n2 / (1.f + n2)) / (n + EPSf);
}

// Grid-wide barrier. All GRID CTAs are co-resident (320 <= 148*3; launch_bounds
// forces >=3 CTAs/SM). Self-resetting counter + monotonic generation, safe
// across graph replays. __threadfence (gpu scope) orders/invalidates L1D.
__device__ __forceinline__ void gridBarrier() {
    __threadfence();          // publish this thread's prior writes
    __syncthreads();          // all CTA threads' writes now fenced
    if (threadIdx.x == 0) {
        unsigned g0 = *(volatile unsigned*)&g_gen;   // capture BEFORE arriving
        unsigned a = atomicAdd(&g_cnt, 1u);
        if (a == GRID - 1) {
            atomicExch(&g_cnt, 0u);                  // reset for next use
            __threadfence();
            atomicAdd(&g_gen, 1u);                   // release waiters
        } else {
            while (*(volatile unsigned*)&g_gen == g0) { }
        }
        __threadfence();      // acquire side
    }
    __syncthreads();
}

// Block sum over 288 threads (9 warps); valid on thread 0.
__device__ __forceinline__ float blockReduceSum288(float v) {
    __shared__ float red[9];
    int lane = threadIdx.x & 31, w = threadIdx.x >> 5;
    #pragma unroll
    for (int o = 16; o > 0; o >>= 1) v += __shfl_down_sync(0xffffffffu, v, o);
    if (lane == 0) red[w] = v;
    __syncthreads();
    float s = 0.f;
    if (threadIdx.x == 0) {
        #pragma unroll
        for (int k = 0; k < 9; k++) s += red[k];
    }
    return s;
}

__global__ void __launch_bounds__(XH, 3) routing_all(
    const float* __restrict__ u, const float* __restrict__ bias,
    float* __restrict__ out)
{
    __shared__ float Us[In][XH + 1];   // resident U tile: 36,992 B
    __shared__ float ss[XH];           // s vector for agreement
    __shared__ float sb[In * Jn];      // routing logits b_ij (identical in all CTAs)
    __shared__ float cs[In];           // coupling coeffs for this CTA's j
    __shared__ float kb_sh[Bn];        // squash scalars
    int bj = blockIdx.x >> 1, half = blockIdx.x & 1;
    int b = bj / Jn, j = bj % Jn;
    int x = threadIdx.x;
    int xg = half * XH + x;
    int w = x >> 5, lane = x & 31;
    float biasv = bias[j * Dn + xg / HWn];

    for (int t = x; t < In * Jn; t += XH) sb[t] = 0.f;

    // ---- Load phase: Us[i][x] = sum_c u_hat[b,i,c,j,xg]  (94 MB streamed once)
    const float* base = u + (size_t)b * In * Cn * Jn * Xn + (size_t)j * Xn + xg;
    #pragma unroll 2
    for (int i = 0; i < In; i++) {
        const float* p = base + (size_t)i * Cn * Jn * Xn;
        float acc = 0.f;
        #pragma unroll
        for (int c = 0; c < Cn; c++) acc += __ldcs(p + (size_t)c * Jn * Xn);
        Us[i][x] = acc;
    }
    __syncthreads();

    float s = 0.f;
    #pragma unroll 1
    for (int iter = 0; iter < 3; iter++) {
        int pb = iter & 1;                        // parity buffer for this iter
        // ---- s_j for this (b,j,half)
        if (iter == 0) {
            float acc = 0.f;
            #pragma unroll
            for (int i = 0; i < In; i++) acc += Us[i][x];
            s = acc * (1.0f / Jn) + biasv;        // softmax(0) = 1/J exactly
        } else {
            float acc = 0.f;
            #pragma unroll
            for (int i = 0; i < In; i++) acc += cs[i] * Us[i][x];
            s = acc + biasv;
        }
        // ---- L1-norm partial
        float n = blockReduceSum288(fabsf(s));
        if (x == 0) g_nPart[pb][blockIdx.x] = n;

        if (iter == 2) break;                     // final agreement is dead

        ss[x] = s;
        __syncthreads();
        // ---- unscaled agreement partials: aU[i] = sum_x Us[i][x]*s[x]
        if (w < 8) {
            #pragma unroll
            for (int ii = 0; ii < 4; ii++) {
                int i = w * 4 + ii;
                float a = 0.f;
                #pragma unroll
                for (int xx = lane; xx < XH; xx += 32) a += Us[i][xx] * ss[xx];
                #pragma unroll
                for (int o = 16; o > 0; o >>= 1) a += __shfl_down_sync(0xffffffffu, a, o);
                if (lane == 0) g_aPart[pb][blockIdx.x * In + i] = a;
            }
        }
        gridBarrier();

        // ---- routing update (computed redundantly & identically by every CTA)
        if (x < Bn) {
            float nn = 0.f;
            #pragma unroll
            for (int t = 0; t < Jn * 2; t++) nn += __ldcg(&g_nPart[pb][x * Jn * 2 + t]);
            kb_sh[x] = squash_k(nn);
        }
        __syncthreads();
        for (int t = x; t < In * Jn; t += XH) {
            int ii = t / Jn, jj = t % Jn;
            float a = 0.f;
            #pragma unroll
            for (int bb = 0; bb < Bn; bb++) {
                float p0 = __ldcg(&g_aPart[pb][(size_t)(((bb * Jn + jj) * 2 + 0) * In) + ii]);
                float p1 = __ldcg(&g_aPart[pb][(size_t)(((bb * Jn + jj) * 2 + 1) * In) + ii]);
                a += kb_sh[bb] * (p0 + p1);
            }
            sb[t] += a;          // b_ij += agreement
        }
        __syncthreads();
        // softmax over j for this CTA's j; threads 0..31 handle i
        if (x < In) {
            float mx = -1e30f;
            #pragma unroll
            for (int jj = 0; jj < Jn; jj++) mx = fmaxf(mx, sb[x * Jn + jj]);
            float den = 0.f;
            #pragma unroll
            for (int jj = 0; jj < Jn; jj++) den += expf(sb[x * Jn + jj] - mx);
            cs[x] = expf(sb[x * Jn + j] - mx) / den;
        }
        __syncthreads();
    }

    // ---- final squash scale needs all batch-b norm partials (iter 2 -> buf 0)
    gridBarrier();
    if (x == 0) {
        float nn = 0.f;
        #pragma unroll
        for (int t = 0; t < Jn * 2; t++) nn += __ldcg(&g_nPart[0][b * Jn * 2 + t]);
        kb_sh[0] = squash_k(nn);
    }
    __syncthreads();
    out[(size_t)bj * Xn + xg] = kb_sh[0] * s;
}

extern "C" void kernel_launch(void* const* d_in, const int* in_sizes, int n_in,
                              void* d_out, int out_size) {
    const float* u    = (const float*)d_in[0];
    const float* bias = (const float*)d_in[1];
    float* out = (float*)d_out;
    routing_all<<<GRID, XH>>>(u, bias, out);
}

// round 5
// speedup vs baseline: 1.0705x; 1.0332x over previous
#include <cuda_runtime.h>

// Shapes (fixed)
#define Bn 16
#define In 32
#define Cn 8
#define Jn 10
#define Dn 16
#define Xn 576   // D*H*W
#define XH 288   // half handled per CTA
#define HWn 36
#define EPSf 1e-7f
#define GRID (Bn*Jn*2)   // 320 CTAs

// Cross-CTA communication scratch, DOUBLE-BUFFERED by iteration parity to kill
// the WAR race across the single per-iteration grid barrier.
__device__ float    g_nPart[2][GRID];        // per-(b,j,half) L1-norm partial of s
__device__ float    g_aPart[2][GRID * In];   // per-(b,j,half) unscaled agreement[i]
__device__ unsigned g_cnt;                   // barrier arrival counter (self-resetting)
__device__ unsigned g_gen;                   // barrier generation (monotonic)

__device__ __forceinline__ float squash_k(float n) {
    float n2 = n * n;
    return (n2 / (1.f + n2)) / (n + EPSf);
}

// Grid-wide barrier. All GRID CTAs are co-resident (320 <= 148*3; launch_bounds
// forces >=3 CTAs/SM). Self-resetting counter + monotonic generation, safe
// across graph replays.
__device__ __forceinline__ void gridBarrier() {
    __threadfence();          // publish this thread's prior writes
    __syncthreads();
    if (threadIdx.x == 0) {
        unsigned g0 = *(volatile unsigned*)&g_gen;   // capture BEFORE arriving
        unsigned a = atomicAdd(&g_cnt, 1u);
        if (a == GRID - 1) {
            atomicExch(&g_cnt, 0u);
            __threadfence();
            atomicAdd(&g_gen, 1u);
        } else {
            while (*(volatile unsigned*)&g_gen == g0) { }
        }
        __threadfence();      // acquire side
    }
    __syncthreads();
}

// Block sum over 288 threads (9 warps); valid on thread 0.
__device__ __forceinline__ float blockReduceSum288(float v) {
    __shared__ float red[9];
    int lane = threadIdx.x & 31, w = threadIdx.x >> 5;
    #pragma unroll
    for (int o = 16; o > 0; o >>= 1) v += __shfl_down_sync(0xffffffffu, v, o);
    if (lane == 0) red[w] = v;
    __syncthreads();
    float s = 0.f;
    if (threadIdx.x == 0) {
        #pragma unroll
        for (int k = 0; k < 9; k++) s += red[k];
    }
    return s;
}

__global__ void __launch_bounds__(XH, 3) routing_all(
    const float* __restrict__ u, const float* __restrict__ bias,
    float* __restrict__ out)
{
    __shared__ __align__(16) float Us[In][XH];  // resident U tile (36,864 B)
    __shared__ float ss[XH];           // s vector for agreement
    __shared__ float sb[In * Jn];      // routing logits b_ij (identical in all CTAs)
    __shared__ float cs[In];           // coupling coeffs for this CTA's j
    __shared__ float kb_sh[Bn];        // squash scalars
    int bj = blockIdx.x >> 1, half = blockIdx.x & 1;
    int b = bj / Jn, j = bj % Jn;
    int x = threadIdx.x;
    int xg = half * XH + x;
    int w = x >> 5, lane = x & 31;
    float biasv = bias[j * Dn + xg / HWn];

    for (int t = x; t < In * Jn; t += XH) sb[t] = 0.f;

    // ---- Load phase (float4, 8 independent lines in flight per thread):
    // Us[i][x] = sum_c u_hat[b,i,c,j,xg]. 94 MB streamed exactly once.
    {
        int t4 = x % 72;          // float4 column: covers 4*t4 .. 4*t4+3 of XH
        int g  = x / 72;          // i-group (0..3), 8 i's each
        int xq = half * XH + t4 * 4;
        const float* base = u + (size_t)b * In * Cn * Jn * Xn + (size_t)j * Xn + xq;
        #pragma unroll 1
        for (int ii = 0; ii < 8; ii++) {
            int i = g * 8 + ii;
            const float4* p = (const float4*)(base + (size_t)i * Cn * Jn * Xn);
            float4 a0 = __ldcs(p);
            float4 a1 = __ldcs(p + 1 * (Jn * Xn / 4));
            float4 a2 = __ldcs(p + 2 * (Jn * Xn / 4));
            float4 a3 = __ldcs(p + 3 * (Jn * Xn / 4));
            float4 a4 = __ldcs(p + 4 * (Jn * Xn / 4));
            float4 a5 = __ldcs(p + 5 * (Jn * Xn / 4));
            float4 a6 = __ldcs(p + 6 * (Jn * Xn / 4));
            float4 a7 = __ldcs(p + 7 * (Jn * Xn / 4));
            float4 acc;
            acc.x = ((a0.x + a1.x) + (a2.x + a3.x)) + ((a4.x + a5.x) + (a6.x + a7.x));
            acc.y = ((a0.y + a1.y) + (a2.y + a3.y)) + ((a4.y + a5.y) + (a6.y + a7.y));
            acc.z = ((a0.z + a1.z) + (a2.z + a3.z)) + ((a4.z + a5.z) + (a6.z + a7.z));
            acc.w = ((a0.w + a1.w) + (a2.w + a3.w)) + ((a4.w + a5.w) + (a6.w + a7.w));
            *(float4*)&Us[i][t4 * 4] = acc;
        }
    }
    __syncthreads();

    float s = 0.f;
    #pragma unroll 1
    for (int iter = 0; iter < 3; iter++) {
        int pb = iter & 1;                        // parity buffer for this iter
        // ---- s_j for this (b,j,half)
        if (iter == 0) {
            float acc = 0.f;
            #pragma unroll
            for (int i = 0; i < In; i++) acc += Us[i][x];
            s = acc * (1.0f / Jn) + biasv;        // softmax(0) = 1/J exactly
        } else {
            float acc = 0.f;
            #pragma unroll
            for (int i = 0; i < In; i++) acc += cs[i] * Us[i][x];
            s = acc + biasv;
        }
        // ---- L1-norm partial
        float n = blockReduceSum288(fabsf(s));
        if (x == 0) g_nPart[pb][blockIdx.x] = n;

        if (iter == 2) break;                     // final agreement is dead

        ss[x] = s;
        __syncthreads();
        // ---- unscaled agreement partials: aU[i] = sum_x Us[i][x]*s[x]
        if (w < 8) {
            #pragma unroll
            for (int ii = 0; ii < 4; ii++) {
                int i = w * 4 + ii;
                float a = 0.f;
                #pragma unroll
                for (int xx = lane; xx < XH; xx += 32) a += Us[i][xx] * ss[xx];
                #pragma unroll
                for (int o = 16; o > 0; o >>= 1) a += __shfl_down_sync(0xffffffffu, a, o);
                if (lane == 0) g_aPart[pb][blockIdx.x * In + i] = a;
            }
        }
        gridBarrier();

        // ---- routing update (computed redundantly & identically by every CTA)
        if (x < Bn) {
            float nn = 0.f;
            #pragma unroll
            for (int t = 0; t < Jn * 2; t++) nn += __ldcg(&g_nPart[pb][x * Jn * 2 + t]);
            kb_sh[x] = squash_k(nn);
        }
        __syncthreads();
        for (int t = x; t < In * Jn; t += XH) {
            int ii = t / Jn, jj = t % Jn;
            float a = 0.f;
            #pragma unroll
            for (int bb = 0; bb < Bn; bb++) {
                float p0 = __ldcg(&g_aPart[pb][(size_t)(((bb * Jn + jj) * 2 + 0) * In) + ii]);
                float p1 = __ldcg(&g_aPart[pb][(size_t)(((bb * Jn + jj) * 2 + 1) * In) + ii]);
                a += kb_sh[bb] * (p0 + p1);
            }
            sb[t] += a;          // b_ij += agreement
        }
        __syncthreads();
        // softmax over j for this CTA's j; threads 0..31 handle i
        if (x < In) {
            float mx = -1e30f;
            #pragma unroll
            for (int jj = 0; jj < Jn; jj++) mx = fmaxf(mx, sb[x * Jn + jj]);
            float den = 0.f;
            #pragma unroll
            for (int jj = 0; jj < Jn; jj++) den += expf(sb[x * Jn + jj] - mx);
            cs[x] = expf(sb[x * Jn + j] - mx) / den;
        }
        __syncthreads();
    }

    // ---- final squash scale needs all batch-b norm partials (iter 2 -> buf 0)
    gridBarrier();
    if (x == 0) {
        float nn = 0.f;
        #pragma unroll
        for (int t = 0; t < Jn * 2; t++) nn += __ldcg(&g_nPart[0][b * Jn * 2 + t]);
        kb_sh[0] = squash_k(nn);
    }
    __syncthreads();
    out[(size_t)bj * Xn + xg] = kb_sh[0] * s;
}

extern "C" void kernel_launch(void* const* d_in, const int* in_sizes, int n_in,
                              void* d_out, int out_size) {
    const float* u    = (const float*)d_in[0];
    const float* bias = (const float*)d_in[1];
    float* out = (float*)d_out;
    routing_all<<<GRID, XH>>>(u, bias, out);
}